// round 10
// baseline (speedup 1.0000x reference)
#include <cuda_runtime.h>
#include <cuda_bf16.h>
#include <cstdint>

// ---------------- Problem dims ----------------
#define M_REAL 200              // T*C rows
#define M_PAD 256               // padded to 16 m16 tiles (hi limb only)
#define KK 16384                // H*W
#define NN 8192                 // D
#define DTILE 64                // d columns per CTA
#define KCH 64                  // k per chunk
#define NCH (KK / KCH)          // 256 chunks
#define NDT (NN / DTILE)        // 128 CTAs
#define THRESH 12.0f

#define ABYTES (M_PAD * 128)    // 32768 per chunk (hi bf16, swizzled)
#define BSTGB (KCH * 272)       // 17408 fp32 staging (256B row + 16B pad)
#define BTILEB (KCH * 144)      // 9216 bf16 tile (pitch 144, no swizzle)
#define STAGEB (ABYTES + BSTGB + BTILEB)   // 59392
#define NSTAGE 3

#define SM_MBAR (NSTAGE * STAGEB)          // 178176
#define SM_SG (SM_MBAR + 32)               // 178208
#define SMEM_TOTAL (SM_SG + 64 * 4)        // 178464

// ---------------- device scratch (static, no runtime allocation) ----------------
__device__ __nv_bfloat16 g_A[NCH * M_PAD * 64];     // 8 MB hi-limb, chunk-tiled+swizzled
__device__ __nv_bfloat16 g_Alo[M_REAL * KK];        // 6.5 MB lo-limb, flat row-major
__device__ float g_score[NN];

// ---------------- PTX helpers ----------------
#define MBAR_INIT(a, c) asm volatile("mbarrier.init.shared.b64 [%0], %1;" :: "r"(a), "r"(c) : "memory")
#define MBAR_EXPECT(a, n) asm volatile("mbarrier.arrive.expect_tx.shared.b64 _, [%0], %1;" :: "r"(a), "r"(n) : "memory")

static __device__ __forceinline__ void mbar_wait(uint32_t mbar, uint32_t parity) {
    asm volatile(
        "{\n\t.reg .pred P1;\n\t"
        "WAIT_LOOP_%=:\n\t"
        "mbarrier.try_wait.parity.acquire.cta.shared::cta.b64 P1, [%0], %1, 0x989680;\n\t"
        "@P1 bra.uni WAIT_DONE_%=;\n\t"
        "bra.uni WAIT_LOOP_%=;\n\t"
        "WAIT_DONE_%=:\n\t}"
        :: "r"(mbar), "r"(parity) : "memory");
}

static __device__ __forceinline__ void bulk_g2s(uint32_t dst, const void* src,
                                                uint32_t bytes, uint32_t mbar) {
    asm volatile(
        "cp.async.bulk.shared::cluster.global.mbarrier::complete_tx::bytes [%0], [%1], %2, [%3];"
        :: "r"(dst), "l"(src), "r"(bytes), "r"(mbar) : "memory");
}

static __device__ __forceinline__ void ldsm_x4(uint32_t* r, uint32_t addr) {
    asm volatile("ldmatrix.sync.aligned.m8n8.x4.shared.b16 {%0,%1,%2,%3}, [%4];"
                 : "=r"(r[0]), "=r"(r[1]), "=r"(r[2]), "=r"(r[3]) : "r"(addr));
}
static __device__ __forceinline__ void ldsm_x2t(uint32_t* r, uint32_t addr) {
    asm volatile("ldmatrix.sync.aligned.m8n8.x2.trans.shared.b16 {%0,%1}, [%2];"
                 : "=r"(r[0]), "=r"(r[1]) : "r"(addr));
}
static __device__ __forceinline__ void mma_bf16(float* c, const uint32_t* a, const uint32_t* b) {
    asm volatile(
        "mma.sync.aligned.m16n8k16.row.col.f32.bf16.bf16.f32 "
        "{%0,%1,%2,%3}, {%4,%5,%6,%7}, {%8,%9}, {%0,%1,%2,%3};"
        : "+f"(c[0]), "+f"(c[1]), "+f"(c[2]), "+f"(c[3])
        : "r"(a[0]), "r"(a[1]), "r"(a[2]), "r"(a[3]), "r"(b[0]), "r"(b[1]));
}

// ---------------- kernel 1: hist -> hi bf16 (chunk-tiled, swizzled) + lo bf16 (flat) ----------------
__global__ void convA(const float* __restrict__ hist) {
    int idx = blockIdx.x * blockDim.x + threadIdx.x;   // 256 m x 2048 units
    int m = idx >> 11;
    int u = idx & 2047;
    int kc = u >> 3, uu = u & 7;
    __nv_bfloat16 hi[8], lo[8];
    if (m < M_REAL) {
        const float* src = hist + (size_t)m * KK + u * 8;
        float4 f0 = *(const float4*)(src);
        float4 f1 = *(const float4*)(src + 4);
        float f[8] = {f0.x, f0.y, f0.z, f0.w, f1.x, f1.y, f1.z, f1.w};
        #pragma unroll
        for (int i = 0; i < 8; i++) {
            hi[i] = __float2bfloat16_rn(f[i]);
            lo[i] = __float2bfloat16_rn(f[i] - __bfloat162float(hi[i]));
        }
    } else {
        #pragma unroll
        for (int i = 0; i < 8; i++) hi[i] = __float2bfloat16_rn(0.f);
    }
    int sw = (uu ^ (m & 7)) * 16;
    *(uint4*)((char*)g_A + (size_t)kc * ABYTES + m * 128 + sw) = *(uint4*)hi;
    if (m < M_REAL)
        *(uint4*)(g_Alo + (size_t)m * KK + u * 8) = *(uint4*)lo;
}

// ---------------- kernel 2: hi bf16 GEMM, bulk pipeline, B converted in-CTA ----------------
__global__ void __launch_bounds__(256)
st_gemm(const float* __restrict__ pos_w,
        const float* __restrict__ time_w,
        const float* __restrict__ pol_w)
{
    extern __shared__ char smem[];
    const uint32_t sbase = (uint32_t)__cvta_generic_to_shared(smem);
    const int tid = threadIdx.x;
    const int w = tid >> 5, lane = tid & 31;
    const int g = lane >> 2, t = lane & 3;
    const int wm = w & 3, wn = w >> 2;      // 4m x 2n warp grid
    const int dt = blockIdx.x;
    const int d0 = dt * DTILE;
    float* sg = (float*)(smem + SM_SG);

    if (tid < NSTAGE) MBAR_INIT(sbase + SM_MBAR + tid * 8, 8);
    if (tid < 64) sg[tid] = 0.0f;
    __syncthreads();

    // distributed issue: lane0 of each warp expects+copies its 8 B rows (+A on warp0)
    auto issue = [&](int c, int s) {
        if (lane == 0) {
            uint32_t mb = sbase + SM_MBAR + s * 8;
            uint32_t stA = sbase + (uint32_t)s * STAGEB;
            uint32_t stG = stA + ABYTES;
            uint32_t bytes = 8 * 256 + (w == 0 ? (uint32_t)ABYTES : 0u);
            MBAR_EXPECT(mb, bytes);
            if (w == 0)
                bulk_g2s(stA, (const char*)g_A + (size_t)c * ABYTES, ABYTES, mb);
            const int kb = c * KCH;
            #pragma unroll
            for (int r = 0; r < 8; r++) {
                int k = w * 8 + r;
                bulk_g2s(stG + (uint32_t)(k * 272),
                         pos_w + (size_t)(kb + k) * NN + d0, 256, mb);
            }
        }
    };

    // fp32 staging -> bf16 tile (pitch 144B, linear), conflict-free
    auto convertB = [&](int s) {
        const float* stg = (const float*)(smem + (size_t)s * STAGEB + ABYTES);
        char* bt = smem + (size_t)s * STAGEB + ABYTES + BSTGB;
        const int k = tid & 63, half = tid >> 6;   // half: 16 floats each
        const float* src = stg + k * 68 + half * 16;
        float4 f0 = *(const float4*)(src);
        float4 f1 = *(const float4*)(src + 4);
        float4 f2 = *(const float4*)(src + 8);
        float4 f3 = *(const float4*)(src + 12);
        __nv_bfloat16 b[16];
        b[0] = __float2bfloat16_rn(f0.x);  b[1] = __float2bfloat16_rn(f0.y);
        b[2] = __float2bfloat16_rn(f0.z);  b[3] = __float2bfloat16_rn(f0.w);
        b[4] = __float2bfloat16_rn(f1.x);  b[5] = __float2bfloat16_rn(f1.y);
        b[6] = __float2bfloat16_rn(f1.z);  b[7] = __float2bfloat16_rn(f1.w);
        b[8] = __float2bfloat16_rn(f2.x);  b[9] = __float2bfloat16_rn(f2.y);
        b[10] = __float2bfloat16_rn(f2.z); b[11] = __float2bfloat16_rn(f2.w);
        b[12] = __float2bfloat16_rn(f3.x); b[13] = __float2bfloat16_rn(f3.y);
        b[14] = __float2bfloat16_rn(f3.z); b[15] = __float2bfloat16_rn(f3.w);
        char* dst = bt + k * 144 + half * 32;
        *(uint4*)(dst) = *(uint4*)(b);
        *(uint4*)(dst + 16) = *(uint4*)(b + 8);
    };

    float acc[4][4][4];
    #pragma unroll
    for (int i = 0; i < 4; i++)
        #pragma unroll
        for (int j = 0; j < 4; j++)
            #pragma unroll
            for (int cc = 0; cc < 4; cc++) acc[i][j][cc] = 0.0f;

    const int Lr = lane & 15;
    const int arow_l = (lane & 7) + ((lane >> 3) & 1) * 8;
    const int asel = lane >> 4;

    auto compute = [&](int s) {
        const uint32_t stA = sbase + (uint32_t)s * STAGEB;
        const uint32_t stB = stA + ABYTES + BSTGB;
        #pragma unroll
        for (int kt = 0; kt < 4; kt++) {
            uint32_t bfr[4][2];
            #pragma unroll
            for (int j = 0; j < 4; j++) {
                int nf = wn * 4 + j;
                int k = kt * 16 + Lr;
                ldsm_x2t(bfr[j], stB + (uint32_t)(k * 144 + nf * 16));
            }
            #pragma unroll
            for (int i = 0; i < 4; i++) {
                int r = (wm + 4 * i) * 16 + arow_l;
                int u = kt * 2 + asel;
                uint32_t a[4];
                ldsm_x4(a, stA + (uint32_t)(r * 128 + ((u ^ (r & 7)) << 4)));
                #pragma unroll
                for (int j = 0; j < 4; j++)
                    mma_bf16(acc[i][j], a, bfr[j]);
            }
        }
    };

    issue(0, 0); issue(1, 1); issue(2, 2);

    for (int c = 0; c < NCH; c++) {
        const int s = c % NSTAGE;
        mbar_wait(sbase + SM_MBAR + s * 8, (uint32_t)((c / NSTAGE) & 1));
        convertB(s);
        __syncthreads();
        compute(s);
        __syncthreads();
        if (c + NSTAGE < NCH) issue(c + NSTAGE, s);
    }

    // ---- epilogue: score[d] = sum_m C[m,d]*time*pol (hi limb only) ----
    {
        float colsum[4][2];
        #pragma unroll
        for (int j = 0; j < 4; j++) { colsum[j][0] = 0.f; colsum[j][1] = 0.f; }
        #pragma unroll
        for (int i = 0; i < 4; i++) {
            int rg = (wm + 4 * i) * 16 + g;
            int m0 = rg, m1 = rg + 8;
            bool v0 = m0 < M_REAL, v1 = m1 < M_REAL;
            #pragma unroll
            for (int j = 0; j < 4; j++) {
                int d = d0 + (wn * 4 + j) * 8 + 2 * t;
                if (v0) {
                    float wa = time_w[(size_t)(m0 >> 1) * NN + d] * pol_w[(size_t)(m0 & 1) * NN + d];
                    float wb = time_w[(size_t)(m0 >> 1) * NN + d + 1] * pol_w[(size_t)(m0 & 1) * NN + d + 1];
                    colsum[j][0] += acc[i][j][0] * wa;
                    colsum[j][1] += acc[i][j][1] * wb;
                }
                if (v1) {
                    float wa = time_w[(size_t)(m1 >> 1) * NN + d] * pol_w[(size_t)(m1 & 1) * NN + d];
                    float wb = time_w[(size_t)(m1 >> 1) * NN + d + 1] * pol_w[(size_t)(m1 & 1) * NN + d + 1];
                    colsum[j][0] += acc[i][j][2] * wa;
                    colsum[j][1] += acc[i][j][3] * wb;
                }
            }
        }
        #pragma unroll
        for (int j = 0; j < 4; j++) {
            #pragma unroll
            for (int cx = 0; cx < 2; cx++) {
                float v = colsum[j][cx];
                v += __shfl_xor_sync(0xFFFFFFFFu, v, 4);
                v += __shfl_xor_sync(0xFFFFFFFFu, v, 8);
                v += __shfl_xor_sync(0xFFFFFFFFu, v, 16);
                if (g == 0)
                    atomicAdd(&sg[(wn * 4 + j) * 8 + 2 * t + cx], v);
            }
        }
    }
    __syncthreads();
    if (tid < 64) g_score[d0 + tid] = sg[tid];
}

// ---------------- kernel 3: lo-limb fixup for |score| < THRESH columns ----------------
// smem: losm 200x128 bf16 (51200) | wsm 200 f (800) | red 256 f (1024) | list 256 int | cnt
#define FX_LO 0
#define FX_WS 51200
#define FX_RED 52000
#define FX_LIST 53024
#define FX_CNT 54048
#define FX_TOTAL 54112

__global__ void __launch_bounds__(256)
st_fix(const float* __restrict__ pos_w,
       const float* __restrict__ time_w,
       const float* __restrict__ pol_w)
{
    extern __shared__ char fsm[];
    __nv_bfloat16* losm = (__nv_bfloat16*)(fsm + FX_LO);
    float* wsm = (float*)(fsm + FX_WS);
    float* red = (float*)(fsm + FX_RED);
    int* list = (int*)(fsm + FX_LIST);
    int* cnt = (int*)(fsm + FX_CNT);
    const int tid = threadIdx.x;
    const int k0 = blockIdx.x * 128;

    // load lo slice [200][128]
    for (int idx = tid; idx < M_REAL * 16; idx += 256) {
        int m = idx >> 4, uu = idx & 15;
        *(uint4*)((char*)losm + m * 256 + uu * 16) =
            *(const uint4*)(g_Alo + (size_t)m * KK + k0 + uu * 8);
    }
    if (tid == 0) *cnt = 0;
    __syncthreads();

    for (int i = 0; i < NN / 256; i++) {
        int d = i * 256 + tid;
        if (fabsf(g_score[d]) < THRESH) {
            int p = atomicAdd(cnt, 1);
            list[p] = d;
        }
    }
    __syncthreads();
    const int nf = *cnt;

    for (int e = 0; e < nf; e++) {
        int d = list[e];
        if (tid < M_REAL)
            wsm[tid] = time_w[(size_t)(tid >> 1) * NN + d] * pol_w[(size_t)(tid & 1) * NN + d];
        __syncthreads();
        float part = 0.0f;
        if (tid < 128) {
            float p = pos_w[(size_t)(k0 + tid) * NN + d];
            float a = 0.0f;
            for (int m = 0; m < M_REAL; m++)
                a += __bfloat162float(losm[m * 128 + tid]) * wsm[m];
            part = p * a;
        }
        red[tid] = part;
        __syncthreads();
        for (int off = 128; off > 0; off >>= 1) {
            if (tid < off) red[tid] += red[tid + off];
            __syncthreads();
        }
        if (tid == 0) atomicAdd(&g_score[d], red[0]);
        __syncthreads();
    }
}

// ---------------- kernel 4: sign ----------------
__global__ void st_sign(float* __restrict__ out) {
    int i = blockIdx.x * blockDim.x + threadIdx.x;
    float v = g_score[i];
    out[i] = (v > 0.0f) ? 1.0f : ((v < 0.0f) ? -1.0f : 0.0f);
}

// ---------------- launch ----------------
extern "C" void kernel_launch(void* const* d_in, const int* in_sizes, int n_in,
                              void* d_out, int out_size) {
    const float* hist   = (const float*)d_in[0];   // [100, 2, 128, 128]
    const float* time_w = (const float*)d_in[1];   // [100, 8192]
    const float* pol_w  = (const float*)d_in[2];   // [2, 8192]
    const float* pos_w  = (const float*)d_in[3];   // [16384, 8192]
    float* out = (float*)d_out;                    // [8192]

    cudaFuncSetAttribute(st_gemm, cudaFuncAttributeMaxDynamicSharedMemorySize, SMEM_TOTAL);
    cudaFuncSetAttribute(st_fix, cudaFuncAttributeMaxDynamicSharedMemorySize, FX_TOTAL);

    convA<<<(M_PAD * 2048) / 256, 256>>>(hist);
    st_gemm<<<NDT, 256, SMEM_TOTAL>>>(pos_w, time_w, pol_w);
    st_fix<<<KK / 128, 256, FX_TOTAL>>>(pos_w, time_w, pol_w);
    st_sign<<<NN / 256, 256>>>(out);
}